// round 8
// baseline (speedup 1.0000x reference)
#include <cuda_runtime.h>
#include <cuda_fp16.h>

#define B_   32
#define T_   4096
#define H_   256
#define S_   256
#define M_   (B_*T_)      // 131072 rows
#define TM_  128          // M tile / segment length
#define NSEG 32           // segments per batch (T/TM_)
#define SEGL 128

// A tile smem: [128 rows][264 fp16]  (row-major, 528B stride: conflict-free ldmatrix)
#define AST 264
// B tile smem: [256 n][40 fp16]      (80B stride: conflict-free ldmatrix)
#define BST 40
#define BUFH (256*BST)        // halves per B buffer
#define BUFB (BUFH*2)         // bytes per B buffer (20480)

// ---------------- scratch (static device globals) ----------------
__device__ __align__(16) __half g_uh[(size_t)M_ * S_];  // segment-LOCAL states, fp16 (64 MB)
__device__ float g_mu[M_];
__device__ float g_rs[M_];
__device__ float g_coeff[S_];
__device__ float g_P[SEGL * S_];           // P[j][s] = coeff[s]^(j+1)
__device__ float g_cl[B_ * NSEG * S_];     // local segment-end states
__device__ float g_ci[B_ * NSEG * S_];     // true state entering each segment
__device__ __align__(16) __half g_W1h[S_*H_];
__device__ __align__(16) __half g_W2h[H_*S_];
__device__ __align__(16) __half g_W3h[H_*H_];

typedef unsigned int u32;

// ---------------- small helpers ----------------
__device__ __forceinline__ unsigned sptr(const void* p){
    return (unsigned)__cvta_generic_to_shared(p);
}
// pack two floats to half2: a -> low 16 bits (element at lower address), b -> high
__device__ __forceinline__ u32 pk2h(float a, float b){
    __half ha = __float2half_rn(a), hb = __float2half_rn(b);
    unsigned short ua = *reinterpret_cast<unsigned short*>(&ha);
    unsigned short ub = *reinterpret_cast<unsigned short*>(&hb);
    return (u32)ua | ((u32)ub << 16);
}
__device__ __forceinline__ float gelu_t(float v){
    float v3 = v * v * v;
    float t  = tanhf(0.7978845608028654f * (v + 0.044715f * v3));
    return 0.5f * v * (1.0f + t);
}

__device__ __forceinline__ void ldsm4(u32 r[4], unsigned addr){
    asm volatile("ldmatrix.sync.aligned.m8n8.x4.shared.b16 {%0,%1,%2,%3}, [%4];"
        : "=r"(r[0]), "=r"(r[1]), "=r"(r[2]), "=r"(r[3]) : "r"(addr));
}
__device__ __forceinline__ void mma_hh(float c[4], const u32 a[4], u32 b0, u32 b1){
    asm volatile("mma.sync.aligned.m16n8k16.row.col.f32.f16.f16.f32 "
        "{%0,%1,%2,%3},{%4,%5,%6,%7},{%8,%9},{%0,%1,%2,%3};"
        : "+f"(c[0]), "+f"(c[1]), "+f"(c[2]), "+f"(c[3])
        : "r"(a[0]), "r"(a[1]), "r"(a[2]), "r"(a[3]), "r"(b0), "r"(b1));
}

// ---------------- fp16 single-pass GEMM core ----------------
// C[128m][256n] += A[128m][256k] @ W^T, W row-major [n][k] fp16.
// 16 warps: warp grid 4(M)x4(N), warp tile 32x64. Accum c[mblk2][n8blk8][4].
// K streamed in 8 chunks of 32 via DOUBLE-BUFFERED Bh smem (one barrier per
// chunk); next chunk's W data register-prefetched so L2 latency hides behind
// the current chunk's mma compute.
//
// WAR safety of the single barrier: at iteration ch we overwrite buffer
// (ch+1)&1, which was last READ during iteration ch-1's compute — i.e. before
// iteration ch-1's trailing barrier. The store of buffer ch&1 (done in
// iteration ch-1) is made visible by that same barrier.
__device__ __forceinline__ void gemm_h(
    const __half* Ah, __half* Bh,           // Bh: 2 buffers of BUFH halves
    const __half* __restrict__ Wh,
    float c[2][8][4], int tid)
{
    const int lane = tid & 31;
    const int w    = tid >> 5;            // 0..15
    const int m0w  = (w >> 2) * 32;
    const int n0w  = (w & 3) * 64;
    const int k4   = tid & 7;             // B-load: which 4-elem group along k
    const int nb   = tid >> 3;            // B-load: base n row (0..63)
    const int lrow = lane & 15;
    const int lc8  = (lane >> 4) * 8;

    const unsigned aAh = sptr(Ah + (m0w + lrow) * AST + lc8);
    const unsigned aBh = sptr(Bh + (n0w + lrow) * BST + lc8);

    uint2 ph[4];
    #pragma unroll
    for (int j = 0; j < 4; j++){
        int n = nb + 64*j;
        ph[j] = *(const uint2*)(Wh + n*256 + k4*4);          // chunk 0
    }
    __syncthreads();        // A tile visible; smem region reusable
    #pragma unroll
    for (int j = 0; j < 4; j++){
        int n = nb + 64*j;
        *(uint2*)(Bh + n*BST + k4*4) = ph[j];                // buf 0
    }
    #pragma unroll
    for (int j = 0; j < 4; j++){
        int n = nb + 64*j;
        ph[j] = *(const uint2*)(Wh + n*256 + 32 + k4*4);     // chunk 1
    }
    __syncthreads();        // buf 0 visible

    for (int ch = 0; ch < 8; ch++){
        if (ch < 7){        // post chunk ch+1 into the other buffer
            __half* Bd = Bh + ((ch+1)&1)*BUFH;
            #pragma unroll
            for (int j = 0; j < 4; j++){
                int n = nb + 64*j;
                *(uint2*)(Bd + n*BST + k4*4) = ph[j];
            }
        }
        if (ch < 6){        // issue loads for chunk ch+2; retire during compute
            #pragma unroll
            for (int j = 0; j < 4; j++){
                int n = nb + 64*j;
                ph[j] = *(const uint2*)(Wh + n*256 + (ch+2)*32 + k4*4);
            }
        }
        const unsigned bufO = (ch & 1) * BUFB;

        #pragma unroll
        for (int ks = 0; ks < 2; ks++){
            const int kA2 = (ch*32 + ks*16) * 2;   // byte offset in A rows
            const int kB2 = (ks*16) * 2;           // byte offset in B rows
            u32 ah[2][4];
            ldsm4(ah[0], aAh + kA2);
            ldsm4(ah[1], aAh + 16*AST*2 + kA2);
            #pragma unroll
            for (int g4 = 0; g4 < 4; g4++){        // 4 groups of n16
                u32 bh[4];
                ldsm4(bh, aBh + bufO + g4*16*BST*2 + kB2);
                #pragma unroll
                for (int mb = 0; mb < 2; mb++){
                    // n-low block: B = {r0, r2}; n-high block: B = {r1, r3}
                    mma_hh(c[mb][g4*2  ], ah[mb], bh[0], bh[2]);
                    mma_hh(c[mb][g4*2+1], ah[mb], bh[1], bh[3]);
                }
            }
        }
        __syncthreads();    // buf (ch+1)&1 visible; buf ch&1 free for overwrite
    }
    // trailing barrier of last iteration protects epilogue overlay writes into A
}

// ---------------- K0a: coefficients + power table ----------------
__global__ void k0c(const float* __restrict__ a, const float* __restrict__ g,
                    const float* __restrict__ dt)
{
    int s = threadIdx.x;
    double d   = (double)dt[s];
    double sp  = log1p(exp(-fabs(d))) + fmax(d, 0.0);
    double dts = sp + 1e-4;
    double gg  = (double)g[s];
    double spg = log1p(exp(-fabs(gg))) + fmax(gg, 0.0);
    double cf  = exp(-2.0 * spg * dts) * cos((double)a[s] * dts);
    g_coeff[s] = (float)cf;
    double p = 1.0;
    for (int j = 0; j < SEGL; j++){ p *= cf; g_P[j*S_ + s] = (float)p; }
}

// ---------------- K0b: weight fp16 conversion ----------------
__global__ void k0w(const float* __restrict__ W1, const float* __restrict__ W2,
                    const float* __restrict__ W3)
{
    int i = blockIdx.x * 256 + threadIdx.x;
    g_W1h[i] = __float2half_rn(W1[i]);
    g_W2h[i] = __float2half_rn(W2[i]);
    g_W3h[i] = __float2half_rn(W3[i]);
}

// ---------------- K1: LN + input GEMM + 128-step local scan ----------------
// smem: U_s overlay region [0, 133120) also holds Ah [0,67584) and the two
// Bh buffers [67584,108544) during the GEMM. w_s/b_s live above 133120.
__global__ void __launch_bounds__(512, 1)
k1(const float* __restrict__ x, const float* __restrict__ nw, const float* __restrict__ nb)
{
    extern __shared__ __align__(16) char smraw[];
    __half* Ah = (__half*)smraw;
    __half* Bh = Ah + TM_*AST;                // 2 buffers
    float* U_s = (float*)smraw;               // overlay (stride 260)
    float* w_s = (float*)(smraw + 133120);
    float* b_s = w_s + 256;

    const int tid = threadIdx.x;
    const int m0  = blockIdx.x * TM_;
    if (tid < 256){ w_s[tid] = nw[tid]; b_s[tid] = nb[tid]; }

    // --- LayerNorm (mu/rs via shuffle; 4 threads per row) ---
    const int mr = tid >> 2, qq = tid & 3;     // mr 0..127
    const float4* xrow = (const float4*)(x + (size_t)(m0 + mr) * H_);
    float s1 = 0.f, s2 = 0.f;
    #pragma unroll
    for (int j = 0; j < 16; j++){
        float4 v = xrow[qq + 4*j];
        s1 += v.x + v.y + v.z + v.w;
        s2 += v.x*v.x + v.y*v.y + v.z*v.z + v.w*v.w;
    }
    s1 += __shfl_xor_sync(0xffffffffu, s1, 1);
    s2 += __shfl_xor_sync(0xffffffffu, s2, 1);
    s1 += __shfl_xor_sync(0xffffffffu, s1, 2);
    s2 += __shfl_xor_sync(0xffffffffu, s2, 2);
    float mu  = s1 * (1.0f / H_);
    float var = s2 * (1.0f / H_) - mu * mu;
    float rs  = rsqrtf(var + 1e-5f);
    if (qq == 0){ g_mu[m0 + mr] = mu; g_rs[m0 + mr] = rs; }

    // make w_s/b_s visible to ALL threads before the normalize loop
    __syncthreads();

    // --- normalize -> fp16 into A ---
    #pragma unroll
    for (int j = 0; j < 16; j++){
        int c0 = 4*(qq + 4*j);
        float4 v = xrow[qq + 4*j];
        float f0 = (v.x - mu) * rs * w_s[c0+0] + b_s[c0+0];
        float f1 = (v.y - mu) * rs * w_s[c0+1] + b_s[c0+1];
        float f2 = (v.z - mu) * rs * w_s[c0+2] + b_s[c0+2];
        float f3 = (v.w - mu) * rs * w_s[c0+3] + b_s[c0+3];
        uint2 ph;
        ph.x = pk2h(f0, f1); ph.y = pk2h(f2, f3);
        *(uint2*)(Ah + mr*AST + c0) = ph;
    }
    // (first __syncthreads inside gemm makes A visible before ldmatrix)

    float c[2][8][4];
    #pragma unroll
    for (int i = 0; i < 2; i++)
        #pragma unroll
        for (int j = 0; j < 8; j++)
            #pragma unroll
            for (int q = 0; q < 4; q++) c[i][j][q] = 0.f;

    gemm_h(Ah, Bh, g_W1h, c, tid);

    // --- dump u into smem scratch (gemm ended with syncthreads) ---
    {
        const int lane = tid & 31, w = tid >> 5;
        const int m0w = (w >> 2) * 32, n0w = (w & 3) * 64;
        const int gg = lane >> 2, tg = lane & 3;
        #pragma unroll
        for (int mb = 0; mb < 2; mb++)
            #pragma unroll
            for (int n8 = 0; n8 < 8; n8++){
                int r0 = m0w + mb*16 + gg;
                int cc = n0w + n8*8 + 2*tg;
                *(float2*)(U_s + r0*260 + cc)     = make_float2(c[mb][n8][0], c[mb][n8][1]);
                *(float2*)(U_s + (r0+8)*260 + cc) = make_float2(c[mb][n8][2], c[mb][n8][3]);
            }
    }
    __syncthreads();

    // --- 128-step local scan along rows, one column per thread (256 threads) ---
    if (tid < 256){
        int s = tid;
        float cf = g_coeff[s];
        float st = 0.f;
        float pre[8];
        #pragma unroll
        for (int j = 0; j < 8; j++) pre[j] = U_s[j*260 + s];
        for (int r0 = 0; r0 < TM_; r0 += 8){
            float cur[8];
            #pragma unroll
            for (int j = 0; j < 8; j++) cur[j] = pre[j];
            if (r0 + 8 < TM_){
                #pragma unroll
                for (int j = 0; j < 8; j++) pre[j] = U_s[(r0+8+j)*260 + s];
            }
            #pragma unroll
            for (int j = 0; j < 8; j++){
                st = fmaf(cf, st, cur[j]);
                U_s[(r0+j)*260 + s] = st;
            }
        }
        int b = m0 >> 12, seg = (m0 >> 7) & (NSEG-1);
        g_cl[(b*NSEG + seg)*S_ + s] = st;
    }
    __syncthreads();

    // --- write local states to global as fp16 ---
    #pragma unroll
    for (int j = 0; j < 16; j++){
        int c0 = 4*(qq + 4*j);
        float4 v = *(const float4*)(U_s + mr*260 + c0);
        uint2 ph;
        ph.x = pk2h(v.x, v.y); ph.y = pk2h(v.z, v.w);
        *(uint2*)(g_uh + (size_t)(m0 + mr)*S_ + c0) = ph;
    }
}

// ---------------- K2b: carry chain across segments (all loads up front) ----------------
__global__ void k2b(const float* __restrict__ st0, float* __restrict__ fin)
{
    int s = threadIdx.x, b = blockIdx.x;
    float cseg = g_P[(SEGL-1)*S_ + s];   // coeff^SEGL
    float ci  = st0[b*S_ + s];
    const float* cl = g_cl + (size_t)b*NSEG*S_ + s;
    float*       cp = g_ci + (size_t)b*NSEG*S_ + s;
    float v[NSEG];
    #pragma unroll
    for (int i = 0; i < NSEG; i++) v[i] = __ldcg(cl + (size_t)i*S_);
    #pragma unroll
    for (int seg = 0; seg < NSEG; seg++){
        cp[(size_t)seg*S_] = ci;
        ci = fmaf(cseg, ci, v[seg]);
    }
    fin[b*S_ + s] = ci;
}

// ---------------- K3: readout GEMM + gelu + output GEMM + residual ----------------
__global__ void __launch_bounds__(512, 1)
k3(const float* __restrict__ x, const float* __restrict__ nw, const float* __restrict__ nb,
   const float* __restrict__ dir, const float* __restrict__ ob, float* __restrict__ y)
{
    extern __shared__ __align__(16) char smraw[];
    __half* Ah = (__half*)smraw;
    __half* Bh = Ah + TM_*AST;                // 2 buffers
    float* w_s  = (float*)(Bh + 2*BUFH);
    float* b_s  = w_s + 256;
    float* d_s  = b_s + 256;
    float* o_s  = d_s + 256;
    float* mu_s = o_s + 256;
    float* rs_s = mu_s + TM_;

    const int tid = threadIdx.x;
    const int m0  = blockIdx.x * TM_;
    if (tid < 256){
        w_s[tid] = nw[tid]; b_s[tid] = nb[tid];
        d_s[tid] = dir[tid]; o_s[tid] = ob[tid];
    }
    if (tid < TM_){ mu_s[tid] = g_mu[m0 + tid]; rs_s[tid] = g_rs[m0 + tid]; }
    // (these are first read in epilogue 2, after gemm's internal barriers)

    // --- load states tile: fp16 local + P[j]*carry -> fp16 into A ---
    const int mr = tid >> 2, qq = tid & 3;     // mr 0..127
    {
        int b = m0 >> 12, seg = (m0 >> 7) & (NSEG-1);
        const __half* lrow = g_uh + (size_t)(m0 + mr) * S_;
        const float* Prow = g_P + mr * S_;                 // j == row-in-tile
        const float* crow = g_ci + (size_t)(b*NSEG + seg) * S_;
        #pragma unroll
        for (int j = 0; j < 16; j++){
            int c0 = 4*(qq + 4*j);
            uint2 lw = *(const uint2*)(lrow + c0);
            __half2 l01 = *reinterpret_cast<__half2*>(&lw.x);
            __half2 l23 = *reinterpret_cast<__half2*>(&lw.y);
            float4 pv = *(const float4*)(Prow + c0);
            float4 cv = *(const float4*)(crow + c0);
            float f0 = fmaf(pv.x, cv.x, __low2float(l01));
            float f1 = fmaf(pv.y, cv.y, __high2float(l01));
            float f2 = fmaf(pv.z, cv.z, __low2float(l23));
            float f3 = fmaf(pv.w, cv.w, __high2float(l23));
            uint2 ph;
            ph.x = pk2h(f0, f1); ph.y = pk2h(f2, f3);
            *(uint2*)(Ah + mr*AST + c0) = ph;
        }
    }

    float c[2][8][4];
    #pragma unroll
    for (int i = 0; i < 2; i++)
        #pragma unroll
        for (int j = 0; j < 8; j++)
            #pragma unroll
            for (int q = 0; q < 4; q++) c[i][j][q] = 0.f;

    // GEMM2: mixed = states @ W2^T
    gemm_h(Ah, Bh, g_W2h, c, tid);

    // --- epilogue 2: + direct*x_norm, gelu -> fp16 back into A ---
    const int lane = tid & 31, w = tid >> 5;
    const int m0w = (w >> 2) * 32, n0w = (w & 3) * 64;
    const int gg = lane >> 2, tg = lane & 3;
    #pragma unroll
    for (int mb = 0; mb < 2; mb++)
        #pragma unroll
        for (int n8 = 0; n8 < 8; n8++){
            int cc = n0w + n8*8 + 2*tg;
            float dw0 = d_s[cc], dw1 = d_s[cc+1];
            float ww0 = w_s[cc], ww1 = w_s[cc+1];
            float bb0 = b_s[cc], bb1 = b_s[cc+1];
            #pragma unroll
            for (int half = 0; half < 2; half++){
                int r = m0w + mb*16 + gg + half*8;
                float2 xv = *(const float2*)(x + (size_t)(m0 + r)*H_ + cc);
                float muv = mu_s[r], rsv = rs_s[r];
                float xn0 = (xv.x - muv) * rsv * ww0 + bb0;
                float xn1 = (xv.y - muv) * rsv * ww1 + bb1;
                float v0 = gelu_t(c[mb][n8][half*2+0] + dw0 * xn0);
                float v1 = gelu_t(c[mb][n8][half*2+1] + dw1 * xn1);
                *(u32*)(Ah + r*AST + cc) = pk2h(v0, v1);
            }
        }
    #pragma unroll
    for (int i = 0; i < 2; i++)
        #pragma unroll
        for (int j = 0; j < 8; j++)
            #pragma unroll
            for (int q = 0; q < 4; q++) c[i][j][q] = 0.f;

    // GEMM3: proj = gelu(mixed) @ W3^T
    gemm_h(Ah, Bh, g_W3h, c, tid);

    // --- epilogue 3: y = x + proj + out_b ---
    #pragma unroll
    for (int mb = 0; mb < 2; mb++)
        #pragma unroll
        for (int n8 = 0; n8 < 8; n8++){
            int cc = n0w + n8*8 + 2*tg;
            float oo0 = o_s[cc], oo1 = o_s[cc+1];
            #pragma unroll
            for (int half = 0; half < 2; half++){
                int r = m0w + mb*16 + gg + half*8;
                float2 xv = *(const float2*)(x + (size_t)(m0 + r)*H_ + cc);
                float2 out;
                out.x = xv.x + c[mb][n8][half*2+0] + oo0;
                out.y = xv.y + c[mb][n8][half*2+1] + oo1;
                *(float2*)(y + (size_t)(m0 + r)*H_ + cc) = out;
            }
        }
}

// ---------------- launcher ----------------
extern "C" void kernel_launch(void* const* d_in, const int* in_sizes, int n_in,
                              void* d_out, int out_size)
{
    const float* x   = (const float*)d_in[0];   // [B,T,H]
    const float* st0 = (const float*)d_in[1];   // [B,S]
    const float* Win = (const float*)d_in[2];   // [S,H]
    const float* W2  = (const float*)d_in[3];   // [H,S]
    const float* dir = (const float*)d_in[4];   // [H]
    const float* ad  = (const float*)d_in[5];   // [S]
    const float* gd  = (const float*)d_in[6];   // [S]
    const float* dt  = (const float*)d_in[7];   // [S]
    const float* nw  = (const float*)d_in[8];   // [H]
    const float* nb  = (const float*)d_in[9];   // [H]
    const float* W3  = (const float*)d_in[10];  // [H,H]
    const float* ob  = (const float*)d_in[11];  // [H]

    float* y   = (float*)d_out;
    float* fin = y + (size_t)M_ * H_;

    const int SMEM1 = 133120 + 2*256*4;                         // U_s overlay + w/b
    const int SMEM3 = (TM_*AST + 2*BUFH)*2 + (256*4 + TM_*2)*4; // 113664
    cudaFuncSetAttribute(k1, cudaFuncAttributeMaxDynamicSharedMemorySize, SMEM1);
    cudaFuncSetAttribute(k3, cudaFuncAttributeMaxDynamicSharedMemorySize, SMEM3);

    k0c<<<1, 256>>>(ad, gd, dt);
    k0w<<<256, 256>>>(Win, W2, W3);
    k1<<<M_/TM_, 512, SMEM1>>>(x, nw, nb);
    k2b<<<B_, 256>>>(st0, fin);
    k3<<<M_/TM_, 512, SMEM3>>>(x, nw, nb, dir, ob, y);
}

// round 9
// speedup vs baseline: 1.5384x; 1.5384x over previous
#include <cuda_runtime.h>
#include <cuda_fp16.h>

#define B_   32
#define T_   4096
#define H_   256
#define S_   256
#define M_   (B_*T_)      // 131072 rows
#define TM_  128          // M tile / segment length
#define NSEG 32           // segments per batch (T/TM_)
#define SEGL 128

// A tile smem: [128 rows][264 fp16]  (528B stride: conflict-free ldmatrix)
#define AST 264
// B tile smem: [256 n][72 fp16] per buffer (144B stride: rows land on 8
// distinct 16B segments mod 128B -> conflict-free ldmatrix). K-chunk = 64.
#define BST 72
#define BUFH (256*BST)        // halves per B buffer (18432)
#define BUFB (BUFH*2)         // bytes per B buffer  (36864)

// ---------------- scratch (static device globals) ----------------
__device__ __align__(16) __half g_uh[(size_t)M_ * S_];  // segment-LOCAL states, fp16
__device__ float g_mu[M_];
__device__ float g_rs[M_];
__device__ float g_coeff[S_];
__device__ float g_P[SEGL * S_];           // P[j][s] = coeff[s]^(j+1)
__device__ float g_cl[B_ * NSEG * S_];     // local segment-end states
__device__ float g_ci[B_ * NSEG * S_];     // true state entering each segment
__device__ __align__(16) __half g_W1h[S_*H_];
__device__ __align__(16) __half g_W2h[H_*S_];
__device__ __align__(16) __half g_W3h[H_*H_];

typedef unsigned int u32;

// ---------------- small helpers ----------------
__device__ __forceinline__ unsigned sptr(const void* p){
    return (unsigned)__cvta_generic_to_shared(p);
}
__device__ __forceinline__ u32 pk2h(float a, float b){
    __half ha = __float2half_rn(a), hb = __float2half_rn(b);
    unsigned short ua = *reinterpret_cast<unsigned short*>(&ha);
    unsigned short ub = *reinterpret_cast<unsigned short*>(&hb);
    return (u32)ua | ((u32)ub << 16);
}
__device__ __forceinline__ float gelu_t(float v){
    float v3 = v * v * v;
    float t  = tanhf(0.7978845608028654f * (v + 0.044715f * v3));
    return 0.5f * v * (1.0f + t);
}
__device__ __forceinline__ void cpa16(unsigned dst, const void* src){
    asm volatile("cp.async.cg.shared.global [%0], [%1], 16;" :: "r"(dst), "l"(src));
}
#define CP_COMMIT() asm volatile("cp.async.commit_group;" ::)
#define CP_WAIT1()  asm volatile("cp.async.wait_group 1;" ::)
#define CP_WAIT0()  asm volatile("cp.async.wait_group 0;" ::)

__device__ __forceinline__ void ldsm4(u32 r[4], unsigned addr){
    asm volatile("ldmatrix.sync.aligned.m8n8.x4.shared.b16 {%0,%1,%2,%3}, [%4];"
        : "=r"(r[0]), "=r"(r[1]), "=r"(r[2]), "=r"(r[3]) : "r"(addr));
}
__device__ __forceinline__ void mma_hh(float c[4], const u32 a[4], u32 b0, u32 b1){
    asm volatile("mma.sync.aligned.m16n8k16.row.col.f32.f16.f16.f32 "
        "{%0,%1,%2,%3},{%4,%5,%6,%7},{%8,%9},{%0,%1,%2,%3};"
        : "+f"(c[0]), "+f"(c[1]), "+f"(c[2]), "+f"(c[3])
        : "r"(a[0]), "r"(a[1]), "r"(a[2]), "r"(a[3]), "r"(b0), "r"(b1));
}

// ---------------- fp16 single-pass GEMM core, cp.async pipelined ----------------
// C[128m][256n] += A[128m][256k] @ W^T, W row-major [n][k] fp16.
// 16 warps: warp grid 4(M)x4(N), warp tile 32x64. Accum c[mblk2][n8blk8][4].
// K in 4 chunks of 64, double-buffered in smem, filled by cp.async so chunk
// ch+2's loads overlap chunk ch's compute (~64 mma/warp of latency cover).
__device__ __forceinline__ void gemm_h(
    const __half* Ah, __half* Bh,           // Bh: 2 buffers of BUFH halves
    const __half* __restrict__ Wh,
    float c[2][8][4], int tid)
{
    const int lane = tid & 31;
    const int w    = tid >> 5;            // 0..15
    const int m0w  = (w >> 2) * 32;
    const int n0w  = (w & 3) * 64;
    const int k16  = tid & 7;             // which 16B group along k (8 per 64-chunk)
    const int nb   = tid >> 3;            // base n row (0..63)
    const int lrow = lane & 15;
    const int lc8  = (lane >> 4) * 8;

    const unsigned aAh = sptr(Ah + (m0w + lrow) * AST + lc8);
    const unsigned aBh = sptr(Bh + (n0w + lrow) * BST + lc8);

    // issue one 64-wide K chunk into a B buffer (4 x 16B per thread)
    const __half* Wsrc = Wh + nb*256 + k16*8;
    #define ISSUE_CHUNK(ch, Bd) do {                                   \
        unsigned d0 = sptr((Bd) + nb*BST + k16*8);                     \
        const __half* s0 = Wsrc + (ch)*64;                             \
        cpa16(d0,                 s0);                                 \
        cpa16(d0 +  64*BST*2, s0 +  64*256);                           \
        cpa16(d0 + 128*BST*2, s0 + 128*256);                           \
        cpa16(d0 + 192*BST*2, s0 + 192*256);                           \
        CP_COMMIT();                                                   \
    } while(0)

    ISSUE_CHUNK(0, Bh);
    ISSUE_CHUNK(1, Bh + BUFH);
    CP_WAIT1();
    __syncthreads();      // buf0 ready everywhere; A tile visible; smem reusable

    for (int ch = 0; ch < 4; ch++){
        const unsigned bufO = (ch & 1) * BUFB;
        #pragma unroll
        for (int ks = 0; ks < 4; ks++){
            const int kA2 = (ch*64 + ks*16) * 2;   // byte offset in A rows
            const int kB2 = (ks*16) * 2;           // byte offset in B rows
            u32 ah[2][4];
            ldsm4(ah[0], aAh + kA2);
            ldsm4(ah[1], aAh + 16*AST*2 + kA2);
            #pragma unroll
            for (int g4 = 0; g4 < 4; g4++){        // 4 groups of n16
                u32 bh[4];
                ldsm4(bh, aBh + bufO + g4*16*BST*2 + kB2);
                #pragma unroll
                for (int mb = 0; mb < 2; mb++){
                    // n-low block: B = {r0, r2}; n-high block: B = {r1, r3}
                    mma_hh(c[mb][g4*2  ], ah[mb], bh[0], bh[2]);
                    mma_hh(c[mb][g4*2+1], ah[mb], bh[1], bh[3]);
                }
            }
        }
        __syncthreads();               // all warps done reading buf ch&1
        if (ch < 2){
            ISSUE_CHUNK(ch+2, Bh + (ch & 1)*BUFH);   // refill the buffer just freed
            CP_WAIT1();                // chunk ch+1 complete
            __syncthreads();
        } else if (ch == 2){
            CP_WAIT0();                // chunk 3 complete
            __syncthreads();
        }
        // ch == 3: trailing barrier above protects epilogue overlay writes into A
    }
    #undef ISSUE_CHUNK
}

// ---------------- K0a: coefficients + power table ----------------
__global__ void k0c(const float* __restrict__ a, const float* __restrict__ g,
                    const float* __restrict__ dt)
{
    int s = threadIdx.x;
    double d   = (double)dt[s];
    double sp  = log1p(exp(-fabs(d))) + fmax(d, 0.0);
    double dts = sp + 1e-4;
    double gg  = (double)g[s];
    double spg = log1p(exp(-fabs(gg))) + fmax(gg, 0.0);
    double cf  = exp(-2.0 * spg * dts) * cos((double)a[s] * dts);
    g_coeff[s] = (float)cf;
    double p = 1.0;
    for (int j = 0; j < SEGL; j++){ p *= cf; g_P[j*S_ + s] = (float)p; }
}

// ---------------- K0b: weight fp16 conversion ----------------
__global__ void k0w(const float* __restrict__ W1, const float* __restrict__ W2,
                    const float* __restrict__ W3)
{
    int i = blockIdx.x * 256 + threadIdx.x;
    g_W1h[i] = __float2half_rn(W1[i]);
    g_W2h[i] = __float2half_rn(W2[i]);
    g_W3h[i] = __float2half_rn(W3[i]);
}

// ---------------- K1: LN + input GEMM + 128-step local scan ----------------
// smem: bytes [0, 141312) = Ah [0,67584) + B bufs [67584,141312) during GEMM;
// same region reused as U_s (stride 260 floats) for the scan. w_s/b_s above.
__global__ void __launch_bounds__(512, 1)
k1(const float* __restrict__ x, const float* __restrict__ nw, const float* __restrict__ nb)
{
    extern __shared__ __align__(16) char smraw[];
    __half* Ah = (__half*)smraw;
    __half* Bh = Ah + TM_*AST;                // 2 buffers
    float* U_s = (float*)smraw;               // overlay (stride 260)
    float* w_s = (float*)(smraw + 141312);
    float* b_s = w_s + 256;

    const int tid = threadIdx.x;
    const int m0  = blockIdx.x * TM_;
    if (tid < 256){ w_s[tid] = nw[tid]; b_s[tid] = nb[tid]; }

    // --- LayerNorm (mu/rs via shuffle; 4 threads per row) ---
    const int mr = tid >> 2, qq = tid & 3;     // mr 0..127
    const float4* xrow = (const float4*)(x + (size_t)(m0 + mr) * H_);
    float s1 = 0.f, s2 = 0.f;
    #pragma unroll
    for (int j = 0; j < 16; j++){
        float4 v = xrow[qq + 4*j];
        s1 += v.x + v.y + v.z + v.w;
        s2 += v.x*v.x + v.y*v.y + v.z*v.z + v.w*v.w;
    }
    s1 += __shfl_xor_sync(0xffffffffu, s1, 1);
    s2 += __shfl_xor_sync(0xffffffffu, s2, 1);
    s1 += __shfl_xor_sync(0xffffffffu, s1, 2);
    s2 += __shfl_xor_sync(0xffffffffu, s2, 2);
    float mu  = s1 * (1.0f / H_);
    float var = s2 * (1.0f / H_) - mu * mu;
    float rs  = rsqrtf(var + 1e-5f);
    if (qq == 0){ g_mu[m0 + mr] = mu; g_rs[m0 + mr] = rs; }

    // make w_s/b_s visible to ALL threads before the normalize loop
    __syncthreads();

    // --- normalize -> fp16 into A ---
    #pragma unroll
    for (int j = 0; j < 16; j++){
        int c0 = 4*(qq + 4*j);
        float4 v = xrow[qq + 4*j];
        float f0 = (v.x - mu) * rs * w_s[c0+0] + b_s[c0+0];
        float f1 = (v.y - mu) * rs * w_s[c0+1] + b_s[c0+1];
        float f2 = (v.z - mu) * rs * w_s[c0+2] + b_s[c0+2];
        float f3 = (v.w - mu) * rs * w_s[c0+3] + b_s[c0+3];
        uint2 ph;
        ph.x = pk2h(f0, f1); ph.y = pk2h(f2, f3);
        *(uint2*)(Ah + mr*AST + c0) = ph;
    }
    // (first __syncthreads inside gemm makes A visible before ldmatrix)

    float c[2][8][4];
    #pragma unroll
    for (int i = 0; i < 2; i++)
        #pragma unroll
        for (int j = 0; j < 8; j++)
            #pragma unroll
            for (int q = 0; q < 4; q++) c[i][j][q] = 0.f;

    gemm_h(Ah, Bh, g_W1h, c, tid);

    // --- dump u into smem scratch (gemm ended with syncthreads) ---
    {
        const int lane = tid & 31, w = tid >> 5;
        const int m0w = (w >> 2) * 32, n0w = (w & 3) * 64;
        const int gg = lane >> 2, tg = lane & 3;
        #pragma unroll
        for (int mb = 0; mb < 2; mb++)
            #pragma unroll
            for (int n8 = 0; n8 < 8; n8++){
                int r0 = m0w + mb*16 + gg;
                int cc = n0w + n8*8 + 2*tg;
                *(float2*)(U_s + r0*260 + cc)     = make_float2(c[mb][n8][0], c[mb][n8][1]);
                *(float2*)(U_s + (r0+8)*260 + cc) = make_float2(c[mb][n8][2], c[mb][n8][3]);
            }
    }
    __syncthreads();

    // --- 128-step local scan along rows, one column per thread (256 threads) ---
    if (tid < 256){
        int s = tid;
        float cf = g_coeff[s];
        float st = 0.f;
        float pre[8];
        #pragma unroll
        for (int j = 0; j < 8; j++) pre[j] = U_s[j*260 + s];
        for (int r0 = 0; r0 < TM_; r0 += 8){
            float cur[8];
            #pragma unroll
            for (int j = 0; j < 8; j++) cur[j] = pre[j];
            if (r0 + 8 < TM_){
                #pragma unroll
                for (int j = 0; j < 8; j++) pre[j] = U_s[(r0+8+j)*260 + s];
            }
            #pragma unroll
            for (int j = 0; j < 8; j++){
                st = fmaf(cf, st, cur[j]);
                U_s[(r0+j)*260 + s] = st;
            }
        }
        int b = m0 >> 12, seg = (m0 >> 7) & (NSEG-1);
        g_cl[(b*NSEG + seg)*S_ + s] = st;
    }
    __syncthreads();

    // --- write local states to global as fp16 ---
    #pragma unroll
    for (int j = 0; j < 16; j++){
        int c0 = 4*(qq + 4*j);
        float4 v = *(const float4*)(U_s + mr*260 + c0);
        uint2 ph;
        ph.x = pk2h(v.x, v.y); ph.y = pk2h(v.z, v.w);
        *(uint2*)(g_uh + (size_t)(m0 + mr)*S_ + c0) = ph;
    }
}

// ---------------- K2b: carry chain across segments (all loads up front) ----------------
__global__ void k2b(const float* __restrict__ st0, float* __restrict__ fin)
{
    int s = threadIdx.x, b = blockIdx.x;
    float cseg = g_P[(SEGL-1)*S_ + s];   // coeff^SEGL
    float ci  = st0[b*S_ + s];
    const float* cl = g_cl + (size_t)b*NSEG*S_ + s;
    float*       cp = g_ci + (size_t)b*NSEG*S_ + s;
    float v[NSEG];
    #pragma unroll
    for (int i = 0; i < NSEG; i++) v[i] = __ldcg(cl + (size_t)i*S_);
    #pragma unroll
    for (int seg = 0; seg < NSEG; seg++){
        cp[(size_t)seg*S_] = ci;
        ci = fmaf(cseg, ci, v[seg]);
    }
    fin[b*S_ + s] = ci;
}

// ---------------- K3: readout GEMM + gelu + output GEMM + residual ----------------
__global__ void __launch_bounds__(512, 1)
k3(const float* __restrict__ x, const float* __restrict__ nw, const float* __restrict__ nb,
   const float* __restrict__ dir, const float* __restrict__ ob, float* __restrict__ y)
{
    extern __shared__ __align__(16) char smraw[];
    __half* Ah = (__half*)smraw;
    __half* Bh = Ah + TM_*AST;                // 2 buffers
    float* w_s  = (float*)(smraw + 141312);
    float* b_s  = w_s + 256;
    float* d_s  = b_s + 256;
    float* o_s  = d_s + 256;
    float* mu_s = o_s + 256;
    float* rs_s = mu_s + TM_;

    const int tid = threadIdx.x;
    const int m0  = blockIdx.x * TM_;
    if (tid < 256){
        w_s[tid] = nw[tid]; b_s[tid] = nb[tid];
        d_s[tid] = dir[tid]; o_s[tid] = ob[tid];
    }
    if (tid < TM_){ mu_s[tid] = g_mu[m0 + tid]; rs_s[tid] = g_rs[m0 + tid]; }
    // (first read in epilogue 2, after gemm's internal barriers)

    // --- load states tile: fp16 local + P[j]*carry -> fp16 into A ---
    const int mr = tid >> 2, qq = tid & 3;     // mr 0..127
    {
        int b = m0 >> 12, seg = (m0 >> 7) & (NSEG-1);
        const __half* lrow = g_uh + (size_t)(m0 + mr) * S_;
        const float* Prow = g_P + mr * S_;                 // j == row-in-tile
        const float* crow = g_ci + (size_t)(b*NSEG + seg) * S_;
        #pragma unroll
        for (int j = 0; j < 16; j++){
            int c0 = 4*(qq + 4*j);
            uint2 lw = *(const uint2*)(lrow + c0);
            __half2 l01 = *reinterpret_cast<__half2*>(&lw.x);
            __half2 l23 = *reinterpret_cast<__half2*>(&lw.y);
            float4 pv = *(const float4*)(Prow + c0);
            float4 cv = *(const float4*)(crow + c0);
            float f0 = fmaf(pv.x, cv.x, __low2float(l01));
            float f1 = fmaf(pv.y, cv.y, __high2float(l01));
            float f2 = fmaf(pv.z, cv.z, __low2float(l23));
            float f3 = fmaf(pv.w, cv.w, __high2float(l23));
            uint2 ph;
            ph.x = pk2h(f0, f1); ph.y = pk2h(f2, f3);
            *(uint2*)(Ah + mr*AST + c0) = ph;
        }
    }

    float c[2][8][4];
    #pragma unroll
    for (int i = 0; i < 2; i++)
        #pragma unroll
        for (int j = 0; j < 8; j++)
            #pragma unroll
            for (int q = 0; q < 4; q++) c[i][j][q] = 0.f;

    // GEMM2: mixed = states @ W2^T
    gemm_h(Ah, Bh, g_W2h, c, tid);

    // --- epilogue 2: + direct*x_norm, gelu -> fp16 back into A ---
    const int lane = tid & 31, w = tid >> 5;
    const int m0w = (w >> 2) * 32, n0w = (w & 3) * 64;
    const int gg = lane >> 2, tg = lane & 3;
    #pragma unroll
    for (int mb = 0; mb < 2; mb++)
        #pragma unroll
        for (int n8 = 0; n8 < 8; n8++){
            int cc = n0w + n8*8 + 2*tg;
            float dw0 = d_s[cc], dw1 = d_s[cc+1];
            float ww0 = w_s[cc], ww1 = w_s[cc+1];
            float bb0 = b_s[cc], bb1 = b_s[cc+1];
            #pragma unroll
            for (int half = 0; half < 2; half++){
                int r = m0w + mb*16 + gg + half*8;
                float2 xv = *(const float2*)(x + (size_t)(m0 + r)*H_ + cc);
                float muv = mu_s[r], rsv = rs_s[r];
                float xn0 = (xv.x - muv) * rsv * ww0 + bb0;
                float xn1 = (xv.y - muv) * rsv * ww1 + bb1;
                float v0 = gelu_t(c[mb][n8][half*2+0] + dw0 * xn0);
                float v1 = gelu_t(c[mb][n8][half*2+1] + dw1 * xn1);
                *(u32*)(Ah + r*AST + cc) = pk2h(v0, v1);
            }
        }
    #pragma unroll
    for (int i = 0; i < 2; i++)
        #pragma unroll
        for (int j = 0; j < 8; j++)
            #pragma unroll
            for (int q = 0; q < 4; q++) c[i][j][q] = 0.f;

    // GEMM3: proj = gelu(mixed) @ W3^T
    gemm_h(Ah, Bh, g_W3h, c, tid);

    // --- epilogue 3: y = x + proj + out_b ---
    #pragma unroll
    for (int mb = 0; mb < 2; mb++)
        #pragma unroll
        for (int n8 = 0; n8 < 8; n8++){
            int cc = n0w + n8*8 + 2*tg;
            float oo0 = o_s[cc], oo1 = o_s[cc+1];
            #pragma unroll
            for (int half = 0; half < 2; half++){
                int r = m0w + mb*16 + gg + half*8;
                float2 xv = *(const float2*)(x + (size_t)(m0 + r)*H_ + cc);
                float2 out;
                out.x = xv.x + c[mb][n8][half*2+0] + oo0;
                out.y = xv.y + c[mb][n8][half*2+1] + oo1;
                *(float2*)(y + (size_t)(m0 + r)*H_ + cc) = out;
            }
        }
}

// ---------------- launcher ----------------
extern "C" void kernel_launch(void* const* d_in, const int* in_sizes, int n_in,
                              void* d_out, int out_size)
{
    const float* x   = (const float*)d_in[0];   // [B,T,H]
    const float* st0 = (const float*)d_in[1];   // [B,S]
    const float* Win = (const float*)d_in[2];   // [S,H]
    const float* W2  = (const float*)d_in[3];   // [H,S]
    const float* dir = (const float*)d_in[4];   // [H]
    const float* ad  = (const float*)d_in[5];   // [S]
    const float* gd  = (const float*)d_in[6];   // [S]
    const float* dt  = (const float*)d_in[7];   // [S]
    const float* nw  = (const float*)d_in[8];   // [H]
    const float* nb  = (const float*)d_in[9];   // [H]
    const float* W3  = (const float*)d_in[10];  // [H,H]
    const float* ob  = (const float*)d_in[11];  // [H]

    float* y   = (float*)d_out;
    float* fin = y + (size_t)M_ * H_;

    const int SMEM1 = 141312 + 2*256*4;                 // A+B region (+U_s overlay) + w/b
    const int SMEM3 = 141312 + (256*4 + TM_*2)*4;       // A+B region + epilogue params
    cudaFuncSetAttribute(k1, cudaFuncAttributeMaxDynamicSharedMemorySize, SMEM1);
    cudaFuncSetAttribute(k3, cudaFuncAttributeMaxDynamicSharedMemorySize, SMEM3);

    k0c<<<1, 256>>>(ad, gd, dt);
    k0w<<<256, 256>>>(Win, W2, W3);
    k1<<<M_/TM_, 512, SMEM1>>>(x, nw, nb);
    k2b<<<B_, 256>>>(st0, fin);
    k3<<<M_/TM_, 512, SMEM3>>>(x, nw, nb, dir, ob, y);
}